// round 12
// baseline (speedup 1.0000x reference)
#include <cuda_runtime.h>
#include <cuda_bf16.h>
#include <cstdint>

#define NN   200000
#define MPAD 200064          // 1563 * 128
#define NE   800000
#define FIN  32
#define HID  128
#define NG   8192
#define NOUT 5

// ---------------- scratch (device globals; no allocations allowed) ----------
__device__ float g_dinv[NN];
__device__ float g_aggA[(size_t)MPAD * FIN];   // layer-0 aggregation (K=32)
__device__ float g_aggP[(size_t)MPAD * HID];   // layer-1 aggregation
__device__ float g_aggQ[(size_t)MPAD * HID];   // layer-2 aggregation
__device__ float g_h[(size_t)MPAD * HID];      // hs = dinv * relu(bn(...))
__device__ float g_pool[NG * HID];
__device__ float g_cnt[NG];
__device__ float g_scale[3 * HID];
__device__ float g_shift[3 * HID];

// ---------------- helpers ----------------------------------------------------
__device__ __forceinline__ void red_add_v4(float* addr, float4 v) {
    asm volatile("red.global.add.v4.f32 [%0], {%1,%2,%3,%4};"
                 :: "l"(addr), "f"(v.x), "f"(v.y), "f"(v.z), "f"(v.w)
                 : "memory");
}

__device__ __forceinline__ void red_add_v2(float* addr, float x, float y) {
    asm volatile("red.global.add.v2.f32 [%0], {%1,%2};"
                 :: "l"(addr), "f"(x), "f"(y)
                 : "memory");
}

__device__ __forceinline__ void mma_bf16(float* d, const uint32_t* a,
                                         uint32_t b0, uint32_t b1) {
    asm volatile("mma.sync.aligned.m16n8k16.row.col.f32.bf16.bf16.f32 "
                 "{%0,%1,%2,%3}, {%4,%5,%6,%7}, {%8,%9}, {%0,%1,%2,%3};"
                 : "+f"(d[0]), "+f"(d[1]), "+f"(d[2]), "+f"(d[3])
                 : "r"(a[0]), "r"(a[1]), "r"(a[2]), "r"(a[3]),
                   "r"(b0), "r"(b1));
}

// split fp32 -> (hi, lo) bf16
__device__ __forceinline__ void bf_split(float v, __nv_bfloat16& h, __nv_bfloat16& l) {
    h = __float2bfloat16_rn(v);
    l = __float2bfloat16_rn(v - __bfloat162float(h));
}

// ---------------- init / degree / counts -------------------------------------
__global__ void k_zero() {
    int i = blockIdx.x * blockDim.x + threadIdx.x;
    if (i < NN)       g_dinv[i] = 0.f;
    if (i < NG * HID) g_pool[i] = 0.f;
    if (i < NG)       g_cnt[i]  = 0.f;
}

__global__ void k_count(const int* __restrict__ col, const int* __restrict__ batch) {
    int e = blockIdx.x * blockDim.x + threadIdx.x;
    if (e < NE) atomicAdd(&g_dinv[col[e]], 1.0f);
    if (e < NN) atomicAdd(&g_cnt[batch[e]], 1.0f);
}

__global__ void k_dinv() {
    int v = blockIdx.x * blockDim.x + threadIdx.x;
    if (v < NN) g_dinv[v] = rsqrtf(g_dinv[v] + 1.0f);
}

__global__ void k_affine(const float* __restrict__ b, const float* __restrict__ ga,
                         const float* __restrict__ be, const float* __restrict__ me,
                         const float* __restrict__ va, int layer) {
    int c = threadIdx.x;
    if (c < HID) {
        float s = ga[c] * rsqrtf(va[c] + 1e-5f);
        g_scale[layer * HID + c] = s;
        g_shift[layer * HID + c] = (b[c] - me[c]) * s + be[c];
    }
}

// ---------------- layer-0 aggregation (from x) --------------------------------
__global__ void k_agg_init0(const float* __restrict__ x) {
    const int Q = FIN / 4;
    int i = blockIdx.x * blockDim.x + threadIdx.x;
    if (i >= NN * Q) return;
    int v = i / Q;
    float dv = g_dinv[v];
    float c = dv * dv;
    float4 a = ((const float4*)x)[i];
    a.x *= c; a.y *= c; a.z *= c; a.w *= c;
    ((float4*)g_aggA)[i] = a;
}

__global__ void k_agg_edges0(const float* __restrict__ x,
                             const int* __restrict__ row, const int* __restrict__ col) {
    const int Q = FIN / 4;
    int i = blockIdx.x * blockDim.x + threadIdx.x;
    if (i >= NE * Q) return;
    int e = i >> 3;
    int q = i & 7;
    int r = row[e], c = col[e];
    float coef = g_dinv[r] * g_dinv[c];
    float4 v = ((const float4*)x)[r * Q + q];
    v.x *= coef; v.y *= coef; v.z *= coef; v.w *= coef;
    red_add_v4(&g_aggA[(size_t)c * FIN + q * 4], v);
}

// ---------------- HID-layer edge scatter: dst += dinv[c] * hs[r] --------------
template<bool TO_Q>
__global__ void k_agg_edges_hs(const int* __restrict__ row, const int* __restrict__ col) {
    int i = blockIdx.x * blockDim.x + threadIdx.x;
    if (i >= NE * 32) return;
    int e = i >> 5;
    int q = i & 31;
    int r = row[e], c = col[e];
    float coef = g_dinv[c];
    float4 v = *(const float4*)&g_h[(size_t)r * HID + q * 4];
    v.x *= coef; v.y *= coef; v.z *= coef; v.w *= coef;
    float* dst = TO_Q ? g_aggQ : g_aggP;
    red_add_v4(&dst[(size_t)c * HID + q * 4], v);
}

// ---------------- SIMT GEMM (layer 0, K=32) ----------------------------------
__global__ __launch_bounds__(256)
void k_gemm0(const float* __restrict__ W) {
    __shared__ float sAt[32][68];
    __shared__ float sB[32][128];

    const int tid = threadIdx.x;
    const int tr  = tid >> 5;
    const int tc  = tid & 31;
    const int row0 = blockIdx.x * 64;

    float acc[8][4];
#pragma unroll
    for (int m = 0; m < 8; m++)
#pragma unroll
        for (int n = 0; n < 4; n++) acc[m][n] = 0.f;

    {
#pragma unroll
        for (int i = 0; i < 2; i++) {
            int l  = tid + 256 * i;
            int r  = l >> 3;
            int k4 = (l & 7) * 4;
            float4 a = *(const float4*)&g_aggA[(size_t)(row0 + r) * FIN + k4];
            sAt[k4 + 0][r] = a.x; sAt[k4 + 1][r] = a.y;
            sAt[k4 + 2][r] = a.z; sAt[k4 + 3][r] = a.w;
        }
#pragma unroll
        for (int i = 0; i < 4; i++) {
            int f  = tid + 256 * i;
            int k  = f >> 5;
            int c4 = (f & 31) * 4;
            *(float4*)&sB[k][c4] = *(const float4*)&W[(size_t)k * 128 + c4];
        }
        __syncthreads();

#pragma unroll
        for (int k = 0; k < 32; k++) {
            float4 a0 = *(const float4*)&sAt[k][tr * 8];
            float4 a1 = *(const float4*)&sAt[k][tr * 8 + 4];
            float4 b  = *(const float4*)&sB[k][tc * 4];
            float av[8] = {a0.x, a0.y, a0.z, a0.w, a1.x, a1.y, a1.z, a1.w};
            float bv[4] = {b.x, b.y, b.z, b.w};
#pragma unroll
            for (int m = 0; m < 8; m++)
#pragma unroll
                for (int n = 0; n < 4; n++)
                    acc[m][n] += av[m] * bv[n];
        }
    }

    int colb = tc * 4;
    float4 s = *(const float4*)&g_scale[colb];
    float4 t = *(const float4*)&g_shift[colb];
#pragma unroll
    for (int m = 0; m < 8; m++) {
        int rr = row0 + tr * 8 + m;
        if (rr < NN) {
            float dv = g_dinv[rr];
            float4 o;
            o.x = fmaxf(acc[m][0] * s.x + t.x, 0.f) * dv;
            o.y = fmaxf(acc[m][1] * s.y + t.y, 0.f) * dv;
            o.z = fmaxf(acc[m][2] * s.z + t.z, 0.f) * dv;
            o.w = fmaxf(acc[m][3] * s.w + t.w, 0.f) * dv;
            *(float4*)&g_h[(size_t)rr * 128 + colb] = o;    // hs
            float4 p = {o.x * dv, o.y * dv, o.z * dv, o.w * dv};
            *(float4*)&g_aggP[(size_t)rr * 128 + colb] = p; // self-loop init
        }
    }
}

// ---------------- bf16-split mma GEMM (layers 1/2, K=128) --------------------
// 2-term split a*b ~= ah*bh + al*bh + ah*bl, all bf16 m16n8k16, fp32 accum.
// Split happens ONCE at smem fill; inner loop is pure LDS.b32 + mma.
// sA: [128 rows][64 k] bf16 stride 72 (hi, lo planes)
// sB: [128 n  ][64 k] bf16 stride 72 (hi, lo planes) — transposed at fill
#define SK_STRIDE 72
#define PLANE_BYTES (128 * SK_STRIDE * 2)      // 18432
#define SM_A_HI 0
#define SM_A_LO (PLANE_BYTES)
#define SM_B_HI (2 * PLANE_BYTES)
#define SM_B_LO (3 * PLANE_BYTES)
#define SM_MMA_BYTES (4 * PLANE_BYTES)         // 73728

template<bool LAST>
__global__ __launch_bounds__(256, 2)
void k_mma(const float* __restrict__ Wm, int layer, const int* __restrict__ batch) {
    extern __shared__ char smem[];
    __nv_bfloat16* sAh = (__nv_bfloat16*)(smem + SM_A_HI);
    __nv_bfloat16* sAl = (__nv_bfloat16*)(smem + SM_A_LO);
    __nv_bfloat16* sBh = (__nv_bfloat16*)(smem + SM_B_HI);
    __nv_bfloat16* sBl = (__nv_bfloat16*)(smem + SM_B_LO);

    const int tid = threadIdx.x;
    const int wid = tid >> 5;
    const int l   = tid & 31;
    const int wr  = wid >> 2;          // 0..1
    const int wc  = wid & 3;           // 0..3
    const size_t row0 = (size_t)blockIdx.x * 128;
    const float* src = LAST ? g_aggQ : g_aggP;

    float acc[4][4][4];
#pragma unroll
    for (int mt = 0; mt < 4; mt++)
#pragma unroll
        for (int nt = 0; nt < 4; nt++)
#pragma unroll
            for (int r = 0; r < 4; r++) acc[mt][nt][r] = 0.f;

    const int lr = l >> 2;             // 0..7
    const int lc = l & 3;              // 0..3

    for (int kc = 0; kc < 2; kc++) {
        // fill A: 128 rows x 64 k, split to hi/lo
#pragma unroll
        for (int it = 0; it < 8; it++) {
            int idx = tid + it * 256;            // 0..2047 float4
            int r   = idx >> 4;
            int q4  = (idx & 15) * 4;
            float4 a = *(const float4*)&src[(row0 + r) * HID + kc * 64 + q4];
            __nv_bfloat16 hx, lx, hy, ly, hz, lz, hw, lw;
            bf_split(a.x, hx, lx); bf_split(a.y, hy, ly);
            bf_split(a.z, hz, lz); bf_split(a.w, hw, lw);
            __nv_bfloat16* ph = &sAh[r * SK_STRIDE + q4];
            __nv_bfloat16* pl = &sAl[r * SK_STRIDE + q4];
            ph[0] = hx; ph[1] = hy; ph[2] = hz; ph[3] = hw;
            pl[0] = lx; pl[1] = ly; pl[2] = lz; pl[3] = lw;
        }
        // fill B transposed: W[k][n] -> sB[n][k], split to hi/lo
#pragma unroll
        for (int it = 0; it < 8; it++) {
            int idx = tid + it * 256;            // 0..2047 float4
            int k   = idx >> 5;                  // 0..63
            int n4  = (idx & 31) * 4;
            float4 b = *(const float4*)&Wm[(size_t)(kc * 64 + k) * HID + n4];
            __nv_bfloat16 h, lo;
            bf_split(b.x, h, lo); sBh[(n4 + 0) * SK_STRIDE + k] = h; sBl[(n4 + 0) * SK_STRIDE + k] = lo;
            bf_split(b.y, h, lo); sBh[(n4 + 1) * SK_STRIDE + k] = h; sBl[(n4 + 1) * SK_STRIDE + k] = lo;
            bf_split(b.z, h, lo); sBh[(n4 + 2) * SK_STRIDE + k] = h; sBl[(n4 + 2) * SK_STRIDE + k] = lo;
            bf_split(b.w, h, lo); sBh[(n4 + 3) * SK_STRIDE + k] = h; sBl[(n4 + 3) * SK_STRIDE + k] = lo;
        }
        __syncthreads();

#pragma unroll
        for (int ks = 0; ks < 4; ks++) {
            const int kk = ks * 16;
            const int kfrag = kk + 2 * lc;       // b32-aligned bf16 pair
            // B fragments (4 n-tiles), hi and lo
            uint32_t bh[4][2], bl[4][2];
#pragma unroll
            for (int nt = 0; nt < 4; nt++) {
                int n = wc * 32 + nt * 8 + lr;
                bh[nt][0] = *(const uint32_t*)&sBh[n * SK_STRIDE + kfrag];
                bh[nt][1] = *(const uint32_t*)&sBh[n * SK_STRIDE + kfrag + 8];
                bl[nt][0] = *(const uint32_t*)&sBl[n * SK_STRIDE + kfrag];
                bl[nt][1] = *(const uint32_t*)&sBl[n * SK_STRIDE + kfrag + 8];
            }
#pragma unroll
            for (int mt = 0; mt < 4; mt++) {
                int r0 = wr * 64 + mt * 16 + lr;
                int r1 = r0 + 8;
                uint32_t ah[4], al[4];
                ah[0] = *(const uint32_t*)&sAh[r0 * SK_STRIDE + kfrag];
                ah[1] = *(const uint32_t*)&sAh[r1 * SK_STRIDE + kfrag];
                ah[2] = *(const uint32_t*)&sAh[r0 * SK_STRIDE + kfrag + 8];
                ah[3] = *(const uint32_t*)&sAh[r1 * SK_STRIDE + kfrag + 8];
                al[0] = *(const uint32_t*)&sAl[r0 * SK_STRIDE + kfrag];
                al[1] = *(const uint32_t*)&sAl[r1 * SK_STRIDE + kfrag];
                al[2] = *(const uint32_t*)&sAl[r0 * SK_STRIDE + kfrag + 8];
                al[3] = *(const uint32_t*)&sAl[r1 * SK_STRIDE + kfrag + 8];
#pragma unroll
                for (int nt = 0; nt < 4; nt++) {
                    mma_bf16(acc[mt][nt], ah, bh[nt][0], bh[nt][1]);
                    mma_bf16(acc[mt][nt], al, bh[nt][0], bh[nt][1]);
                    mma_bf16(acc[mt][nt], ah, bl[nt][0], bl[nt][1]);
                }
            }
        }
        __syncthreads();
    }

    // epilogue (accumulator layout identical to m16n8k8)
    float2 sc[4], sh[4];
#pragma unroll
    for (int nt = 0; nt < 4; nt++) {
        int c = wc * 32 + nt * 8 + 2 * lc;
        sc[nt] = *(const float2*)&g_scale[layer * HID + c];
        sh[nt] = *(const float2*)&g_shift[layer * HID + c];
    }
#pragma unroll
    for (int mt = 0; mt < 4; mt++) {
        size_t r0a = row0 + wr * 64 + mt * 16 + lr;
        size_t r1a = r0a + 8;
        if (LAST) {
            int b0 = (r0a < NN) ? batch[r0a] : -1;
            int b1 = (r1a < NN) ? batch[r1a] : -1;
#pragma unroll
            for (int nt = 0; nt < 4; nt++) {
                int c = wc * 32 + nt * 8 + 2 * lc;
                if (b0 >= 0) {
                    float ox = fmaxf(acc[mt][nt][0] * sc[nt].x + sh[nt].x, 0.f);
                    float oy = fmaxf(acc[mt][nt][1] * sc[nt].y + sh[nt].y, 0.f);
                    red_add_v2(&g_pool[b0 * HID + c], ox, oy);
                }
                if (b1 >= 0) {
                    float ox = fmaxf(acc[mt][nt][2] * sc[nt].x + sh[nt].x, 0.f);
                    float oy = fmaxf(acc[mt][nt][3] * sc[nt].y + sh[nt].y, 0.f);
                    red_add_v2(&g_pool[b1 * HID + c], ox, oy);
                }
            }
        } else {
            float dv0 = (r0a < NN) ? g_dinv[r0a] : 0.f;
            float dv1 = (r1a < NN) ? g_dinv[r1a] : 0.f;
#pragma unroll
            for (int nt = 0; nt < 4; nt++) {
                int c = wc * 32 + nt * 8 + 2 * lc;
                if (r0a < NN) {
                    float hx = fmaxf(acc[mt][nt][0] * sc[nt].x + sh[nt].x, 0.f) * dv0;
                    float hy = fmaxf(acc[mt][nt][1] * sc[nt].y + sh[nt].y, 0.f) * dv0;
                    *(float2*)&g_h[r0a * HID + c]    = {hx, hy};
                    *(float2*)&g_aggQ[r0a * HID + c] = {hx * dv0, hy * dv0};
                }
                if (r1a < NN) {
                    float hx = fmaxf(acc[mt][nt][2] * sc[nt].x + sh[nt].x, 0.f) * dv1;
                    float hy = fmaxf(acc[mt][nt][3] * sc[nt].y + sh[nt].y, 0.f) * dv1;
                    *(float2*)&g_h[r1a * HID + c]    = {hx, hy};
                    *(float2*)&g_aggQ[r1a * HID + c] = {hx * dv1, hy * dv1};
                }
            }
        }
    }
}

// ---------------- output ------------------------------------------------------
__global__ void k_out(const float* __restrict__ Wout, const float* __restrict__ bout,
                      float* __restrict__ out) {
    int i = blockIdx.x * blockDim.x + threadIdx.x;
    if (i >= NG * NOUT) return;
    int g = i / NOUT, o = i - g * NOUT;
    float inv = 1.0f / fmaxf(g_cnt[g], 1.0f);
    const float* p = &g_pool[g * HID];
    float s = 0.f;
#pragma unroll 8
    for (int k = 0; k < HID; k++) s += p[k] * Wout[k * NOUT + o];
    out[i] = s * inv + bout[o];
}

// ---------------- launch -----------------------------------------------------
extern "C" void kernel_launch(void* const* d_in, const int* in_sizes, int n_in,
                              void* d_out, int out_size) {
    const float* x     = (const float*)d_in[0];
    const int*   ei    = (const int*)d_in[1];
    const int*   batch = (const int*)d_in[2];
    const float* W0 = (const float*)d_in[3];
    const float* b0 = (const float*)d_in[4];
    const float* ga0 = (const float*)d_in[5];
    const float* be0 = (const float*)d_in[6];
    const float* me0 = (const float*)d_in[7];
    const float* va0 = (const float*)d_in[8];
    const float* W1 = (const float*)d_in[9];
    const float* b1 = (const float*)d_in[10];
    const float* ga1 = (const float*)d_in[11];
    const float* be1 = (const float*)d_in[12];
    const float* me1 = (const float*)d_in[13];
    const float* va1 = (const float*)d_in[14];
    const float* W2 = (const float*)d_in[15];
    const float* b2 = (const float*)d_in[16];
    const float* ga2 = (const float*)d_in[17];
    const float* be2 = (const float*)d_in[18];
    const float* me2 = (const float*)d_in[19];
    const float* va2 = (const float*)d_in[20];
    const float* Wout = (const float*)d_in[21];
    const float* bout = (const float*)d_in[22];
    float* out = (float*)d_out;

    const int* row = ei;
    const int* col = ei + NE;

    cudaFuncSetAttribute(k_mma<false>, cudaFuncAttributeMaxDynamicSharedMemorySize, SM_MMA_BYTES);
    cudaFuncSetAttribute(k_mma<true>,  cudaFuncAttributeMaxDynamicSharedMemorySize, SM_MMA_BYTES);

    k_zero<<<(NG * HID + 255) / 256, 256>>>();
    k_count<<<(NE + 255) / 256, 256>>>(col, batch);
    k_dinv<<<(NN + 255) / 256, 256>>>();
    k_affine<<<1, 128>>>(b0, ga0, be0, me0, va0, 0);
    k_affine<<<1, 128>>>(b1, ga1, be1, me1, va1, 1);
    k_affine<<<1, 128>>>(b2, ga2, be2, me2, va2, 2);

    // layer 0: aggregate x into aggA, GEMM -> hs + aggP init
    k_agg_init0<<<(NN * (FIN / 4) + 255) / 256, 256>>>(x);
    k_agg_edges0<<<(NE * (FIN / 4) + 255) / 256, 256>>>(x, row, col);
    k_gemm0<<<MPAD / 64, 256>>>(W0);

    // layer 1: edges add dinv[c]*hs[r] into aggP; mma -> hs + aggQ init
    k_agg_edges_hs<false><<<(NE * 32 + 255) / 256, 256>>>(row, col);
    k_mma<false><<<MPAD / 128, 256, SM_MMA_BYTES>>>(W1, 1, batch);

    // layer 2: edges into aggQ; mma -> pool atomics
    k_agg_edges_hs<true><<<(NE * 32 + 255) / 256, 256>>>(row, col);
    k_mma<true><<<MPAD / 128, 256, SM_MMA_BYTES>>>(W2, 2, batch);

    // output
    k_out<<<(NG * NOUT + 255) / 256, 256>>>(Wout, bout, out);
}

// round 14
// speedup vs baseline: 1.2588x; 1.2588x over previous
#include <cuda_runtime.h>
#include <cuda_bf16.h>
#include <cstdint>

#define NN   200000
#define MPAD 200064          // 1563 * 128
#define NE   800000
#define FIN  32
#define HID  128
#define NG   8192
#define NOUT 5

// ---------------- scratch (device globals; no allocations allowed) ----------
__device__ float g_dinv[NN];
__device__ float g_aggA[(size_t)MPAD * FIN];   // layer-0 aggregation (K=32)
__device__ float g_aggP[(size_t)MPAD * HID];   // layer-1 aggregation
__device__ float g_aggQ[(size_t)MPAD * HID];   // layer-2 aggregation
__device__ float g_h[(size_t)MPAD * HID];      // hs = dinv * relu(bn(...))
__device__ float g_pool[NG * HID];
__device__ float g_cnt[NG];
__device__ float g_scale[3 * HID];
__device__ float g_shift[3 * HID];

// ---------------- helpers ----------------------------------------------------
__device__ __forceinline__ void red_add_v4(float* addr, float4 v) {
    asm volatile("red.global.add.v4.f32 [%0], {%1,%2,%3,%4};"
                 :: "l"(addr), "f"(v.x), "f"(v.y), "f"(v.z), "f"(v.w)
                 : "memory");
}

__device__ __forceinline__ void red_add_v2(float* addr, float x, float y) {
    asm volatile("red.global.add.v2.f32 [%0], {%1,%2};"
                 :: "l"(addr), "f"(x), "f"(y)
                 : "memory");
}

__device__ __forceinline__ void mma_bf16(float* d, const uint32_t* a,
                                         uint32_t b0, uint32_t b1) {
    asm volatile("mma.sync.aligned.m16n8k16.row.col.f32.bf16.bf16.f32 "
                 "{%0,%1,%2,%3}, {%4,%5,%6,%7}, {%8,%9}, {%0,%1,%2,%3};"
                 : "+f"(d[0]), "+f"(d[1]), "+f"(d[2]), "+f"(d[3])
                 : "r"(a[0]), "r"(a[1]), "r"(a[2]), "r"(a[3]),
                   "r"(b0), "r"(b1));
}

// split two floats -> packed hi-pair u32 and lo-pair u32 (bf16x2; low half = first)
__device__ __forceinline__ void split2(float x, float y, uint32_t& hi, uint32_t& lo) {
    __nv_bfloat16 hx = __float2bfloat16_rn(x);
    __nv_bfloat16 hy = __float2bfloat16_rn(y);
    float lx = x - __bfloat162float(hx);
    float ly = y - __bfloat162float(hy);
    __nv_bfloat162 h = __halves2bfloat162(hx, hy);
    __nv_bfloat162 l = __floats2bfloat162_rn(lx, ly);
    hi = *(uint32_t*)&h;
    lo = *(uint32_t*)&l;
}

// ---------------- init / degree / counts -------------------------------------
__global__ void k_zero() {
    int i = blockIdx.x * blockDim.x + threadIdx.x;
    if (i < NN)       g_dinv[i] = 0.f;
    if (i < NG * HID) g_pool[i] = 0.f;
    if (i < NG)       g_cnt[i]  = 0.f;
}

__global__ void k_count(const int* __restrict__ col, const int* __restrict__ batch) {
    int e = blockIdx.x * blockDim.x + threadIdx.x;
    if (e < NE) atomicAdd(&g_dinv[col[e]], 1.0f);
    if (e < NN) atomicAdd(&g_cnt[batch[e]], 1.0f);
}

__global__ void k_dinv() {
    int v = blockIdx.x * blockDim.x + threadIdx.x;
    if (v < NN) g_dinv[v] = rsqrtf(g_dinv[v] + 1.0f);
}

__global__ void k_affine(const float* __restrict__ b, const float* __restrict__ ga,
                         const float* __restrict__ be, const float* __restrict__ me,
                         const float* __restrict__ va, int layer) {
    int c = threadIdx.x;
    if (c < HID) {
        float s = ga[c] * rsqrtf(va[c] + 1e-5f);
        g_scale[layer * HID + c] = s;
        g_shift[layer * HID + c] = (b[c] - me[c]) * s + be[c];
    }
}

// ---------------- layer-0 aggregation (from x) --------------------------------
__global__ void k_agg_init0(const float* __restrict__ x) {
    const int Q = FIN / 4;
    int i = blockIdx.x * blockDim.x + threadIdx.x;
    if (i >= NN * Q) return;
    int v = i / Q;
    float dv = g_dinv[v];
    float c = dv * dv;
    float4 a = ((const float4*)x)[i];
    a.x *= c; a.y *= c; a.z *= c; a.w *= c;
    ((float4*)g_aggA)[i] = a;
}

__global__ void k_agg_edges0(const float* __restrict__ x,
                             const int* __restrict__ row, const int* __restrict__ col) {
    const int Q = FIN / 4;
    int i = blockIdx.x * blockDim.x + threadIdx.x;
    if (i >= NE * Q) return;
    int e = i >> 3;
    int q = i & 7;
    int r = row[e], c = col[e];
    float coef = g_dinv[r] * g_dinv[c];
    float4 v = ((const float4*)x)[r * Q + q];
    v.x *= coef; v.y *= coef; v.z *= coef; v.w *= coef;
    red_add_v4(&g_aggA[(size_t)c * FIN + q * 4], v);
}

// ---------------- HID-layer edge scatter: dst += dinv[c] * hs[r] --------------
template<bool TO_Q>
__global__ void k_agg_edges_hs(const int* __restrict__ row, const int* __restrict__ col) {
    int i = blockIdx.x * blockDim.x + threadIdx.x;
    if (i >= NE * 32) return;
    int e = i >> 5;
    int q = i & 31;
    int r = row[e], c = col[e];
    float coef = g_dinv[c];
    float4 v = *(const float4*)&g_h[(size_t)r * HID + q * 4];
    v.x *= coef; v.y *= coef; v.z *= coef; v.w *= coef;
    float* dst = TO_Q ? g_aggQ : g_aggP;
    red_add_v4(&dst[(size_t)c * HID + q * 4], v);
}

// ---------------- SIMT GEMM (layer 0, K=32) ----------------------------------
__global__ __launch_bounds__(256)
void k_gemm0(const float* __restrict__ W) {
    __shared__ float sAt[32][68];
    __shared__ float sB[32][128];

    const int tid = threadIdx.x;
    const int tr  = tid >> 5;
    const int tc  = tid & 31;
    const int row0 = blockIdx.x * 64;

    float acc[8][4];
#pragma unroll
    for (int m = 0; m < 8; m++)
#pragma unroll
        for (int n = 0; n < 4; n++) acc[m][n] = 0.f;

    {
#pragma unroll
        for (int i = 0; i < 2; i++) {
            int l  = tid + 256 * i;
            int r  = l >> 3;
            int k4 = (l & 7) * 4;
            float4 a = *(const float4*)&g_aggA[(size_t)(row0 + r) * FIN + k4];
            sAt[k4 + 0][r] = a.x; sAt[k4 + 1][r] = a.y;
            sAt[k4 + 2][r] = a.z; sAt[k4 + 3][r] = a.w;
        }
#pragma unroll
        for (int i = 0; i < 4; i++) {
            int f  = tid + 256 * i;
            int k  = f >> 5;
            int c4 = (f & 31) * 4;
            *(float4*)&sB[k][c4] = *(const float4*)&W[(size_t)k * 128 + c4];
        }
        __syncthreads();

#pragma unroll
        for (int k = 0; k < 32; k++) {
            float4 a0 = *(const float4*)&sAt[k][tr * 8];
            float4 a1 = *(const float4*)&sAt[k][tr * 8 + 4];
            float4 b  = *(const float4*)&sB[k][tc * 4];
            float av[8] = {a0.x, a0.y, a0.z, a0.w, a1.x, a1.y, a1.z, a1.w};
            float bv[4] = {b.x, b.y, b.z, b.w};
#pragma unroll
            for (int m = 0; m < 8; m++)
#pragma unroll
                for (int n = 0; n < 4; n++)
                    acc[m][n] += av[m] * bv[n];
        }
    }

    int colb = tc * 4;
    float4 s = *(const float4*)&g_scale[colb];
    float4 t = *(const float4*)&g_shift[colb];
#pragma unroll
    for (int m = 0; m < 8; m++) {
        int rr = row0 + tr * 8 + m;
        if (rr < NN) {
            float dv = g_dinv[rr];
            float4 o;
            o.x = fmaxf(acc[m][0] * s.x + t.x, 0.f) * dv;
            o.y = fmaxf(acc[m][1] * s.y + t.y, 0.f) * dv;
            o.z = fmaxf(acc[m][2] * s.z + t.z, 0.f) * dv;
            o.w = fmaxf(acc[m][3] * s.w + t.w, 0.f) * dv;
            *(float4*)&g_h[(size_t)rr * 128 + colb] = o;    // hs
            float4 p = {o.x * dv, o.y * dv, o.z * dv, o.w * dv};
            *(float4*)&g_aggP[(size_t)rr * 128 + colb] = p; // self-loop init
        }
    }
}

// ---------------- bf16 k-pair-packed mma GEMM (layers 1/2, K=128) ------------
// 2-term split a*b ~= ah*bh + al*bh + ah*bl, m16n8k16, fp32 accum.
// SMEM holds PACKED bf16 k-pairs (uint32 = (k, k+1)) — the exact mma register
// format — so fragment loads are single b32 LDS and the loop has zero cvt.
//   A planes: uint32 [128 rows][36]   (32 kpairs + pad; banks 4r+c distinct)
//   B planes: uint32 [32 kpairs][136] (n contiguous; banks 8k2+n distinct)
#define SA_U32 36
#define SB_U32 136
#define A_PLANE_U32 (128 * SA_U32)     // 4608
#define B_PLANE_U32 (32 * SB_U32)      // 4352
#define SM_MMA_BYTES ((2 * A_PLANE_U32 + 2 * B_PLANE_U32) * 4)   // 71680

template<bool LAST>
__global__ __launch_bounds__(256, 2)
void k_mma(const float* __restrict__ Wm, int layer, const int* __restrict__ batch) {
    extern __shared__ uint32_t smem_u[];
    uint32_t* sAh = smem_u;
    uint32_t* sAl = smem_u + A_PLANE_U32;
    uint32_t* sBh = smem_u + 2 * A_PLANE_U32;
    uint32_t* sBl = smem_u + 2 * A_PLANE_U32 + B_PLANE_U32;

    const int tid = threadIdx.x;
    const int wid = tid >> 5;
    const int l   = tid & 31;
    const int wr  = wid >> 2;          // 0..1
    const int wc  = wid & 3;           // 0..3
    const size_t row0 = (size_t)blockIdx.x * 128;
    const float* src = LAST ? g_aggQ : g_aggP;

    float acc[4][4][4];
#pragma unroll
    for (int mt = 0; mt < 4; mt++)
#pragma unroll
        for (int nt = 0; nt < 4; nt++)
#pragma unroll
            for (int r = 0; r < 4; r++) acc[mt][nt][r] = 0.f;

    const int lr = l >> 2;             // 0..7
    const int lc = l & 3;              // 0..3

    for (int kc = 0; kc < 2; kc++) {
        // ---- fill A: 128 rows x 64 k -> packed pairs, uint2 stores ----
#pragma unroll
        for (int it = 0; it < 8; it++) {
            int idx = tid + it * 256;            // 0..2047
            int r   = idx >> 4;                  // 0..127
            int q4  = (idx & 15) * 4;            // k offset 0..60
            float4 a = *(const float4*)&src[(row0 + r) * HID + kc * 64 + q4];
            uint32_t h0, l0, h1, l1;
            split2(a.x, a.y, h0, l0);
            split2(a.z, a.w, h1, l1);
            int o = r * SA_U32 + (q4 >> 1);      // kpair index
            *(uint2*)&sAh[o] = {h0, h1};
            *(uint2*)&sAl[o] = {l0, l1};
        }
        // ---- fill B: 32 kpairs x 128 n -> packed pairs, uint4 stores ----
#pragma unroll
        for (int it = 0; it < 4; it++) {
            int idx = tid + it * 256;            // 0..1023
            int k2  = idx >> 5;                  // 0..31
            int n4  = (idx & 31) * 4;            // 0..124
            const float* w0 = &Wm[(size_t)(kc * 64 + 2 * k2) * HID + n4];
            float4 be = *(const float4*)w0;          // k even
            float4 bo = *(const float4*)(w0 + HID);  // k odd
            uint32_t h[4], lo[4];
            split2(be.x, bo.x, h[0], lo[0]);
            split2(be.y, bo.y, h[1], lo[1]);
            split2(be.z, bo.z, h[2], lo[2]);
            split2(be.w, bo.w, h[3], lo[3]);
            int o = k2 * SB_U32 + n4;
            *(uint4*)&sBh[o] = {h[0], h[1], h[2], h[3]};
            *(uint4*)&sBl[o] = {lo[0], lo[1], lo[2], lo[3]};
        }
        __syncthreads();

        // ---- mainloop: 4 k16 steps per chunk, pure LDS + mma ----
#pragma unroll
        for (int ks = 0; ks < 4; ks++) {
            const int base = ks * 8;             // kpair base
            uint32_t bh[4][2], bl[4][2];
#pragma unroll
            for (int nt = 0; nt < 4; nt++) {
                int n = wc * 32 + nt * 8 + lr;
                bh[nt][0] = sBh[(base + lc) * SB_U32 + n];
                bh[nt][1] = sBh[(base + 4 + lc) * SB_U32 + n];
                bl[nt][0] = sBl[(base + lc) * SB_U32 + n];
                bl[nt][1] = sBl[(base + 4 + lc) * SB_U32 + n];
            }
#pragma unroll
            for (int mt = 0; mt < 4; mt++) {
                int r0 = wr * 64 + mt * 16 + lr;
                int r1 = r0 + 8;
                uint32_t ah[4], al[4];
                ah[0] = sAh[r0 * SA_U32 + base + lc];
                ah[1] = sAh[r1 * SA_U32 + base + lc];
                ah[2] = sAh[r0 * SA_U32 + base + 4 + lc];
                ah[3] = sAh[r1 * SA_U32 + base + 4 + lc];
                al[0] = sAl[r0 * SA_U32 + base + lc];
                al[1] = sAl[r1 * SA_U32 + base + lc];
                al[2] = sAl[r0 * SA_U32 + base + 4 + lc];
                al[3] = sAl[r1 * SA_U32 + base + 4 + lc];
#pragma unroll
                for (int nt = 0; nt < 4; nt++) {
                    mma_bf16(acc[mt][nt], ah, bh[nt][0], bh[nt][1]);
                    mma_bf16(acc[mt][nt], al, bh[nt][0], bh[nt][1]);
                    mma_bf16(acc[mt][nt], ah, bl[nt][0], bl[nt][1]);
                }
            }
        }
        __syncthreads();
    }

    // ---- epilogue (same accumulator layout as m16n8k8) ----
    float2 sc[4], sh[4];
#pragma unroll
    for (int nt = 0; nt < 4; nt++) {
        int c = wc * 32 + nt * 8 + 2 * lc;
        sc[nt] = *(const float2*)&g_scale[layer * HID + c];
        sh[nt] = *(const float2*)&g_shift[layer * HID + c];
    }
#pragma unroll
    for (int mt = 0; mt < 4; mt++) {
        size_t r0a = row0 + wr * 64 + mt * 16 + lr;
        size_t r1a = r0a + 8;
        if (LAST) {
            int b0 = (r0a < NN) ? batch[r0a] : -1;
            int b1 = (r1a < NN) ? batch[r1a] : -1;
#pragma unroll
            for (int nt = 0; nt < 4; nt++) {
                int c = wc * 32 + nt * 8 + 2 * lc;
                if (b0 >= 0) {
                    float ox = fmaxf(acc[mt][nt][0] * sc[nt].x + sh[nt].x, 0.f);
                    float oy = fmaxf(acc[mt][nt][1] * sc[nt].y + sh[nt].y, 0.f);
                    red_add_v2(&g_pool[b0 * HID + c], ox, oy);
                }
                if (b1 >= 0) {
                    float ox = fmaxf(acc[mt][nt][2] * sc[nt].x + sh[nt].x, 0.f);
                    float oy = fmaxf(acc[mt][nt][3] * sc[nt].y + sh[nt].y, 0.f);
                    red_add_v2(&g_pool[b1 * HID + c], ox, oy);
                }
            }
        } else {
            float dv0 = (r0a < NN) ? g_dinv[r0a] : 0.f;
            float dv1 = (r1a < NN) ? g_dinv[r1a] : 0.f;
#pragma unroll
            for (int nt = 0; nt < 4; nt++) {
                int c = wc * 32 + nt * 8 + 2 * lc;
                if (r0a < NN) {
                    float hx = fmaxf(acc[mt][nt][0] * sc[nt].x + sh[nt].x, 0.f) * dv0;
                    float hy = fmaxf(acc[mt][nt][1] * sc[nt].y + sh[nt].y, 0.f) * dv0;
                    *(float2*)&g_h[r0a * HID + c]    = {hx, hy};
                    *(float2*)&g_aggQ[r0a * HID + c] = {hx * dv0, hy * dv0};
                }
                if (r1a < NN) {
                    float hx = fmaxf(acc[mt][nt][2] * sc[nt].x + sh[nt].x, 0.f) * dv1;
                    float hy = fmaxf(acc[mt][nt][3] * sc[nt].y + sh[nt].y, 0.f) * dv1;
                    *(float2*)&g_h[r1a * HID + c]    = {hx, hy};
                    *(float2*)&g_aggQ[r1a * HID + c] = {hx * dv1, hy * dv1};
                }
            }
        }
    }
}

// ---------------- output ------------------------------------------------------
__global__ void k_out(const float* __restrict__ Wout, const float* __restrict__ bout,
                      float* __restrict__ out) {
    int i = blockIdx.x * blockDim.x + threadIdx.x;
    if (i >= NG * NOUT) return;
    int g = i / NOUT, o = i - g * NOUT;
    float inv = 1.0f / fmaxf(g_cnt[g], 1.0f);
    const float* p = &g_pool[g * HID];
    float s = 0.f;
#pragma unroll 8
    for (int k = 0; k < HID; k++) s += p[k] * Wout[k * NOUT + o];
    out[i] = s * inv + bout[o];
}

// ---------------- launch -----------------------------------------------------
extern "C" void kernel_launch(void* const* d_in, const int* in_sizes, int n_in,
                              void* d_out, int out_size) {
    const float* x     = (const float*)d_in[0];
    const int*   ei    = (const int*)d_in[1];
    const int*   batch = (const int*)d_in[2];
    const float* W0 = (const float*)d_in[3];
    const float* b0 = (const float*)d_in[4];
    const float* ga0 = (const float*)d_in[5];
    const float* be0 = (const float*)d_in[6];
    const float* me0 = (const float*)d_in[7];
    const float* va0 = (const float*)d_in[8];
    const float* W1 = (const float*)d_in[9];
    const float* b1 = (const float*)d_in[10];
    const float* ga1 = (const float*)d_in[11];
    const float* be1 = (const float*)d_in[12];
    const float* me1 = (const float*)d_in[13];
    const float* va1 = (const float*)d_in[14];
    const float* W2 = (const float*)d_in[15];
    const float* b2 = (const float*)d_in[16];
    const float* ga2 = (const float*)d_in[17];
    const float* be2 = (const float*)d_in[18];
    const float* me2 = (const float*)d_in[19];
    const float* va2 = (const float*)d_in[20];
    const float* Wout = (const float*)d_in[21];
    const float* bout = (const float*)d_in[22];
    float* out = (float*)d_out;

    const int* row = ei;
    const int* col = ei + NE;

    cudaFuncSetAttribute(k_mma<false>, cudaFuncAttributeMaxDynamicSharedMemorySize, SM_MMA_BYTES);
    cudaFuncSetAttribute(k_mma<true>,  cudaFuncAttributeMaxDynamicSharedMemorySize, SM_MMA_BYTES);

    k_zero<<<(NG * HID + 255) / 256, 256>>>();
    k_count<<<(NE + 255) / 256, 256>>>(col, batch);
    k_dinv<<<(NN + 255) / 256, 256>>>();
    k_affine<<<1, 128>>>(b0, ga0, be0, me0, va0, 0);
    k_affine<<<1, 128>>>(b1, ga1, be1, me1, va1, 1);
    k_affine<<<1, 128>>>(b2, ga2, be2, me2, va2, 2);

    // layer 0: aggregate x into aggA, GEMM -> hs + aggP init
    k_agg_init0<<<(NN * (FIN / 4) + 255) / 256, 256>>>(x);
    k_agg_edges0<<<(NE * (FIN / 4) + 255) / 256, 256>>>(x, row, col);
    k_gemm0<<<MPAD / 64, 256>>>(W0);

    // layer 1: edges add dinv[c]*hs[r] into aggP; mma -> hs + aggQ init
    k_agg_edges_hs<false><<<(NE * 32 + 255) / 256, 256>>>(row, col);
    k_mma<false><<<MPAD / 128, 256, SM_MMA_BYTES>>>(W1, 1, batch);

    // layer 2: edges into aggQ; mma -> pool atomics
    k_agg_edges_hs<true><<<(NE * 32 + 255) / 256, 256>>>(row, col);
    k_mma<true><<<MPAD / 128, 256, SM_MMA_BYTES>>>(W2, 2, batch);

    // output
    k_out<<<(NG * NOUT + 255) / 256, 256>>>(Wout, bout, out);
}

// round 15
// speedup vs baseline: 1.6341x; 1.2981x over previous
#include <cuda_runtime.h>
#include <cuda_bf16.h>
#include <cstdint>

#define NN   200000
#define MPAD 200064          // 1563 * 128
#define NE   800000
#define FIN  32
#define HID  128
#define NG   8192
#define NOUT 5
#define NB_SCAN 196          // ceil(NN / 1024)

// ---------------- scratch (device globals; no allocations allowed) ----------
__device__ float g_dinv[NN];
__device__ int   g_ideg[NN];
__device__ int   g_off[NN];
__device__ int   g_pos[NN];
__device__ int   g_csr_src[NE];
__device__ int   g_bsum[256];
__device__ int   g_boff[256];
__device__ float g_xs[(size_t)NN * FIN];       // dinv * x
__device__ float g_aggA[(size_t)MPAD * FIN];   // layer-0 aggregation (K=32)
__device__ float g_aggP[(size_t)MPAD * HID];   // layer-1 aggregation
__device__ float g_aggQ[(size_t)MPAD * HID];   // layer-2 aggregation
__device__ float g_h[(size_t)MPAD * HID];      // hs = dinv * relu(bn(...))
__device__ float g_pool[NG * HID];
__device__ float g_cnt[NG];
__device__ float g_scale[3 * HID];
__device__ float g_shift[3 * HID];

// ---------------- helpers ----------------------------------------------------
__device__ __forceinline__ void red_add_v2(float* addr, float x, float y) {
    asm volatile("red.global.add.v2.f32 [%0], {%1,%2};"
                 :: "l"(addr), "f"(x), "f"(y)
                 : "memory");
}

__device__ __forceinline__ void mma_bf16(float* d, const uint32_t* a,
                                         uint32_t b0, uint32_t b1) {
    asm volatile("mma.sync.aligned.m16n8k16.row.col.f32.bf16.bf16.f32 "
                 "{%0,%1,%2,%3}, {%4,%5,%6,%7}, {%8,%9}, {%0,%1,%2,%3};"
                 : "+f"(d[0]), "+f"(d[1]), "+f"(d[2]), "+f"(d[3])
                 : "r"(a[0]), "r"(a[1]), "r"(a[2]), "r"(a[3]),
                   "r"(b0), "r"(b1));
}

// split two floats -> packed hi-pair u32 and lo-pair u32 (bf16x2; low half = first)
__device__ __forceinline__ void split2(float x, float y, uint32_t& hi, uint32_t& lo) {
    __nv_bfloat16 hx = __float2bfloat16_rn(x);
    __nv_bfloat16 hy = __float2bfloat16_rn(y);
    float lx = x - __bfloat162float(hx);
    float ly = y - __bfloat162float(hy);
    __nv_bfloat162 h = __halves2bfloat162(hx, hy);
    __nv_bfloat162 l = __floats2bfloat162_rn(lx, ly);
    hi = *(uint32_t*)&h;
    lo = *(uint32_t*)&l;
}

// ---------------- init / degree / counts -------------------------------------
__global__ void k_zero() {
    int i = blockIdx.x * blockDim.x + threadIdx.x;
    if (i < NN)       g_ideg[i] = 0;
    if (i < NG * HID) g_pool[i] = 0.f;
    if (i < NG)       g_cnt[i]  = 0.f;
}

__global__ void k_hist(const int* __restrict__ col, const int* __restrict__ batch) {
    int e = blockIdx.x * blockDim.x + threadIdx.x;
    if (e < NE) atomicAdd(&g_ideg[col[e]], 1);
    if (e < NN) atomicAdd(&g_cnt[batch[e]], 1.0f);
}

__global__ void k_dinv() {
    int v = blockIdx.x * blockDim.x + threadIdx.x;
    if (v < NN) g_dinv[v] = rsqrtf((float)g_ideg[v] + 1.0f);
}

// ---------------- exclusive scan of g_ideg -> g_off (3 kernels) --------------
__global__ void k_scan1() {
    __shared__ int wsum[8];
    int t = threadIdx.x;                       // 0..255
    int base = blockIdx.x * 1024 + t * 4;
    int d0 = (base + 0 < NN) ? g_ideg[base + 0] : 0;
    int d1 = (base + 1 < NN) ? g_ideg[base + 1] : 0;
    int d2 = (base + 2 < NN) ? g_ideg[base + 2] : 0;
    int d3 = (base + 3 < NN) ? g_ideg[base + 3] : 0;
    int tot = d0 + d1 + d2 + d3;
    int lane = t & 31, w = t >> 5;
    int x = tot;
#pragma unroll
    for (int d = 1; d < 32; d <<= 1) {
        int y = __shfl_up_sync(0xffffffff, x, d);
        if (lane >= d) x += y;
    }
    if (lane == 31) wsum[w] = x;
    __syncthreads();
    if (t < 8) {
        int v = wsum[t];
#pragma unroll
        for (int d = 1; d < 8; d <<= 1) {
            int y = __shfl_up_sync(0xff, v, d);
            if (t >= d) v += y;
        }
        wsum[t] = v;                           // inclusive
    }
    __syncthreads();
    int warp_excl = (w > 0) ? wsum[w - 1] : 0;
    int excl = warp_excl + (x - tot);
    if (base + 0 < NN) g_off[base + 0] = excl;
    if (base + 1 < NN) g_off[base + 1] = excl + d0;
    if (base + 2 < NN) g_off[base + 2] = excl + d0 + d1;
    if (base + 3 < NN) g_off[base + 3] = excl + d0 + d1 + d2;
    if (t == 255) g_bsum[blockIdx.x] = wsum[7];
}

__global__ void k_scan2() {
    __shared__ int wsum[8];
    int t = threadIdx.x;
    int v = (t < NB_SCAN) ? g_bsum[t] : 0;
    int lane = t & 31, w = t >> 5;
    int x = v;
#pragma unroll
    for (int d = 1; d < 32; d <<= 1) {
        int y = __shfl_up_sync(0xffffffff, x, d);
        if (lane >= d) x += y;
    }
    if (lane == 31) wsum[w] = x;
    __syncthreads();
    if (t < 8) {
        int s = wsum[t];
#pragma unroll
        for (int d = 1; d < 8; d <<= 1) {
            int y = __shfl_up_sync(0xff, s, d);
            if (t >= d) s += y;
        }
        wsum[t] = s;
    }
    __syncthreads();
    int excl = ((w > 0) ? wsum[w - 1] : 0) + x - v;
    if (t < NB_SCAN) g_boff[t] = excl;
}

__global__ void k_scan3() {
    int i = blockIdx.x * blockDim.x + threadIdx.x;
    if (i < NN) {
        int o = g_off[i] + g_boff[i >> 10];
        g_off[i] = o;
        g_pos[i] = o;
    }
}

__global__ void k_fill(const int* __restrict__ row, const int* __restrict__ col) {
    int e = blockIdx.x * blockDim.x + threadIdx.x;
    if (e < NE) {
        int c = col[e];
        int slot = atomicAdd(&g_pos[c], 1);
        g_csr_src[slot] = row[e];
    }
}

// ---------------- affine fold --------------------------------------------------
__global__ void k_affine(const float* __restrict__ b, const float* __restrict__ ga,
                         const float* __restrict__ be, const float* __restrict__ me,
                         const float* __restrict__ va, int layer) {
    int c = threadIdx.x;
    if (c < HID) {
        float s = ga[c] * rsqrtf(va[c] + 1e-5f);
        g_scale[layer * HID + c] = s;
        g_shift[layer * HID + c] = (b[c] - me[c]) * s + be[c];
    }
}

// ---------------- layer-0: xs = dinv*x, then CSR aggregation ------------------
__global__ void k_xs(const float* __restrict__ x) {
    int i = blockIdx.x * blockDim.x + threadIdx.x;
    if (i >= NN * 8) return;
    int v = i >> 3;
    float dv = g_dinv[v];
    float4 a = ((const float4*)x)[i];
    a.x *= dv; a.y *= dv; a.z *= dv; a.w *= dv;
    ((float4*)g_xs)[i] = a;
}

__global__ void k_agg0() {
    int i = blockIdx.x * blockDim.x + threadIdx.x;
    if (i >= NN * 8) return;
    int v = i >> 3, q = i & 7;
    int off = g_off[v], deg = g_ideg[v];
    const float4* xs4 = (const float4*)g_xs;
    float4 acc = xs4[(size_t)v * 8 + q];                // self term (xs[v])
    for (int j = 0; j < deg; j++) {
        int s = g_csr_src[off + j];
        float4 t = xs4[(size_t)s * 8 + q];
        acc.x += t.x; acc.y += t.y; acc.z += t.z; acc.w += t.w;
    }
    float dv = g_dinv[v];
    acc.x *= dv; acc.y *= dv; acc.z *= dv; acc.w *= dv;
    *(float4*)&g_aggA[(size_t)v * FIN + q * 4] = acc;
}

// ---------------- HID-layer CSR aggregation: agg[v] = dinv[v]*(hs[v]+Σhs[r]) --
template<bool TO_Q>
__global__ void k_agg_h() {
    int i = blockIdx.x * blockDim.x + threadIdx.x;
    int v = i >> 5;
    if (v >= NN) return;
    int lane = i & 31;
    int off = g_off[v], deg = g_ideg[v];
    const float4* h4 = (const float4*)g_h;
    float4 acc = h4[(size_t)v * 32 + lane];             // self term (hs[v])
    for (int j = 0; j < deg; j++) {
        int s = g_csr_src[off + j];
        float4 t = h4[(size_t)s * 32 + lane];
        acc.x += t.x; acc.y += t.y; acc.z += t.z; acc.w += t.w;
    }
    float dv = g_dinv[v];
    acc.x *= dv; acc.y *= dv; acc.z *= dv; acc.w *= dv;
    float* dst = TO_Q ? g_aggQ : g_aggP;
    *(float4*)&dst[(size_t)v * HID + lane * 4] = acc;
}

// ---------------- SIMT GEMM (layer 0, K=32) ----------------------------------
__global__ __launch_bounds__(256)
void k_gemm0(const float* __restrict__ W) {
    __shared__ float sAt[32][68];
    __shared__ float sB[32][128];

    const int tid = threadIdx.x;
    const int tr  = tid >> 5;
    const int tc  = tid & 31;
    const int row0 = blockIdx.x * 64;

    float acc[8][4];
#pragma unroll
    for (int m = 0; m < 8; m++)
#pragma unroll
        for (int n = 0; n < 4; n++) acc[m][n] = 0.f;

    {
#pragma unroll
        for (int i = 0; i < 2; i++) {
            int l  = tid + 256 * i;
            int r  = l >> 3;
            int k4 = (l & 7) * 4;
            int rr = row0 + r;
            float4 a = (rr < NN) ? *(const float4*)&g_aggA[(size_t)rr * FIN + k4]
                                 : make_float4(0.f, 0.f, 0.f, 0.f);
            sAt[k4 + 0][r] = a.x; sAt[k4 + 1][r] = a.y;
            sAt[k4 + 2][r] = a.z; sAt[k4 + 3][r] = a.w;
        }
#pragma unroll
        for (int i = 0; i < 4; i++) {
            int f  = tid + 256 * i;
            int k  = f >> 5;
            int c4 = (f & 31) * 4;
            *(float4*)&sB[k][c4] = *(const float4*)&W[(size_t)k * 128 + c4];
        }
        __syncthreads();

#pragma unroll
        for (int k = 0; k < 32; k++) {
            float4 a0 = *(const float4*)&sAt[k][tr * 8];
            float4 a1 = *(const float4*)&sAt[k][tr * 8 + 4];
            float4 b  = *(const float4*)&sB[k][tc * 4];
            float av[8] = {a0.x, a0.y, a0.z, a0.w, a1.x, a1.y, a1.z, a1.w};
            float bv[4] = {b.x, b.y, b.z, b.w};
#pragma unroll
            for (int m = 0; m < 8; m++)
#pragma unroll
                for (int n = 0; n < 4; n++)
                    acc[m][n] += av[m] * bv[n];
        }
    }

    int colb = tc * 4;
    float4 s = *(const float4*)&g_scale[colb];
    float4 t = *(const float4*)&g_shift[colb];
#pragma unroll
    for (int m = 0; m < 8; m++) {
        int rr = row0 + tr * 8 + m;
        if (rr < NN) {
            float dv = g_dinv[rr];
            float4 o;
            o.x = fmaxf(acc[m][0] * s.x + t.x, 0.f) * dv;
            o.y = fmaxf(acc[m][1] * s.y + t.y, 0.f) * dv;
            o.z = fmaxf(acc[m][2] * s.z + t.z, 0.f) * dv;
            o.w = fmaxf(acc[m][3] * s.w + t.w, 0.f) * dv;
            *(float4*)&g_h[(size_t)rr * 128 + colb] = o;    // hs only
        }
    }
}

// ---------------- bf16 k-pair-packed mma GEMM (layers 1/2, K=128) ------------
#define SA_U32 36
#define SB_U32 136
#define A_PLANE_U32 (128 * SA_U32)
#define B_PLANE_U32 (32 * SB_U32)
#define SM_MMA_BYTES ((2 * A_PLANE_U32 + 2 * B_PLANE_U32) * 4)   // 71680

template<bool LAST>
__global__ __launch_bounds__(256, 2)
void k_mma(const float* __restrict__ Wm, int layer, const int* __restrict__ batch) {
    extern __shared__ uint32_t smem_u[];
    uint32_t* sAh = smem_u;
    uint32_t* sAl = smem_u + A_PLANE_U32;
    uint32_t* sBh = smem_u + 2 * A_PLANE_U32;
    uint32_t* sBl = smem_u + 2 * A_PLANE_U32 + B_PLANE_U32;

    const int tid = threadIdx.x;
    const int wid = tid >> 5;
    const int l   = tid & 31;
    const int wr  = wid >> 2;
    const int wc  = wid & 3;
    const size_t row0 = (size_t)blockIdx.x * 128;
    const float* src = LAST ? g_aggQ : g_aggP;

    float acc[4][4][4];
#pragma unroll
    for (int mt = 0; mt < 4; mt++)
#pragma unroll
        for (int nt = 0; nt < 4; nt++)
#pragma unroll
            for (int r = 0; r < 4; r++) acc[mt][nt][r] = 0.f;

    const int lr = l >> 2;
    const int lc = l & 3;

    for (int kc = 0; kc < 2; kc++) {
        // fill A (rows beyond NN read garbage scratch — never used for outputs)
#pragma unroll
        for (int it = 0; it < 8; it++) {
            int idx = tid + it * 256;
            int r   = idx >> 4;
            int q4  = (idx & 15) * 4;
            size_t rr = row0 + r;
            float4 a = (rr < NN) ? *(const float4*)&src[rr * HID + kc * 64 + q4]
                                 : make_float4(0.f, 0.f, 0.f, 0.f);
            uint32_t h0, l0, h1, l1;
            split2(a.x, a.y, h0, l0);
            split2(a.z, a.w, h1, l1);
            int o = r * SA_U32 + (q4 >> 1);
            *(uint2*)&sAh[o] = {h0, h1};
            *(uint2*)&sAl[o] = {l0, l1};
        }
#pragma unroll
        for (int it = 0; it < 4; it++) {
            int idx = tid + it * 256;
            int k2  = idx >> 5;
            int n4  = (idx & 31) * 4;
            const float* w0 = &Wm[(size_t)(kc * 64 + 2 * k2) * HID + n4];
            float4 be = *(const float4*)w0;
            float4 bo = *(const float4*)(w0 + HID);
            uint32_t h[4], lo[4];
            split2(be.x, bo.x, h[0], lo[0]);
            split2(be.y, bo.y, h[1], lo[1]);
            split2(be.z, bo.z, h[2], lo[2]);
            split2(be.w, bo.w, h[3], lo[3]);
            int o = k2 * SB_U32 + n4;
            *(uint4*)&sBh[o] = {h[0], h[1], h[2], h[3]};
            *(uint4*)&sBl[o] = {lo[0], lo[1], lo[2], lo[3]};
        }
        __syncthreads();

#pragma unroll
        for (int ks = 0; ks < 4; ks++) {
            const int base = ks * 8;
            uint32_t bh[4][2], bl[4][2];
#pragma unroll
            for (int nt = 0; nt < 4; nt++) {
                int n = wc * 32 + nt * 8 + lr;
                bh[nt][0] = sBh[(base + lc) * SB_U32 + n];
                bh[nt][1] = sBh[(base + 4 + lc) * SB_U32 + n];
                bl[nt][0] = sBl[(base + lc) * SB_U32 + n];
                bl[nt][1] = sBl[(base + 4 + lc) * SB_U32 + n];
            }
#pragma unroll
            for (int mt = 0; mt < 4; mt++) {
                int r0 = wr * 64 + mt * 16 + lr;
                int r1 = r0 + 8;
                uint32_t ah[4], al[4];
                ah[0] = sAh[r0 * SA_U32 + base + lc];
                ah[1] = sAh[r1 * SA_U32 + base + lc];
                ah[2] = sAh[r0 * SA_U32 + base + 4 + lc];
                ah[3] = sAh[r1 * SA_U32 + base + 4 + lc];
                al[0] = sAl[r0 * SA_U32 + base + lc];
                al[1] = sAl[r1 * SA_U32 + base + lc];
                al[2] = sAl[r0 * SA_U32 + base + 4 + lc];
                al[3] = sAl[r1 * SA_U32 + base + 4 + lc];
#pragma unroll
                for (int nt = 0; nt < 4; nt++) {
                    mma_bf16(acc[mt][nt], ah, bh[nt][0], bh[nt][1]);
                    mma_bf16(acc[mt][nt], al, bh[nt][0], bh[nt][1]);
                    mma_bf16(acc[mt][nt], ah, bl[nt][0], bl[nt][1]);
                }
            }
        }
        __syncthreads();
    }

    // epilogue
    float2 sc[4], sh[4];
#pragma unroll
    for (int nt = 0; nt < 4; nt++) {
        int c = wc * 32 + nt * 8 + 2 * lc;
        sc[nt] = *(const float2*)&g_scale[layer * HID + c];
        sh[nt] = *(const float2*)&g_shift[layer * HID + c];
    }
#pragma unroll
    for (int mt = 0; mt < 4; mt++) {
        size_t r0a = row0 + wr * 64 + mt * 16 + lr;
        size_t r1a = r0a + 8;
        if (LAST) {
            int b0 = (r0a < NN) ? batch[r0a] : -1;
            int b1 = (r1a < NN) ? batch[r1a] : -1;
#pragma unroll
            for (int nt = 0; nt < 4; nt++) {
                int c = wc * 32 + nt * 8 + 2 * lc;
                if (b0 >= 0) {
                    float ox = fmaxf(acc[mt][nt][0] * sc[nt].x + sh[nt].x, 0.f);
                    float oy = fmaxf(acc[mt][nt][1] * sc[nt].y + sh[nt].y, 0.f);
                    red_add_v2(&g_pool[b0 * HID + c], ox, oy);
                }
                if (b1 >= 0) {
                    float ox = fmaxf(acc[mt][nt][2] * sc[nt].x + sh[nt].x, 0.f);
                    float oy = fmaxf(acc[mt][nt][3] * sc[nt].y + sh[nt].y, 0.f);
                    red_add_v2(&g_pool[b1 * HID + c], ox, oy);
                }
            }
        } else {
            float dv0 = (r0a < NN) ? g_dinv[r0a] : 0.f;
            float dv1 = (r1a < NN) ? g_dinv[r1a] : 0.f;
#pragma unroll
            for (int nt = 0; nt < 4; nt++) {
                int c = wc * 32 + nt * 8 + 2 * lc;
                if (r0a < NN) {
                    float hx = fmaxf(acc[mt][nt][0] * sc[nt].x + sh[nt].x, 0.f) * dv0;
                    float hy = fmaxf(acc[mt][nt][1] * sc[nt].y + sh[nt].y, 0.f) * dv0;
                    *(float2*)&g_h[r0a * HID + c] = {hx, hy};
                }
                if (r1a < NN) {
                    float hx = fmaxf(acc[mt][nt][2] * sc[nt].x + sh[nt].x, 0.f) * dv1;
                    float hy = fmaxf(acc[mt][nt][3] * sc[nt].y + sh[nt].y, 0.f) * dv1;
                    *(float2*)&g_h[r1a * HID + c] = {hx, hy};
                }
            }
        }
    }
}

// ---------------- output ------------------------------------------------------
__global__ void k_out(const float* __restrict__ Wout, const float* __restrict__ bout,
                      float* __restrict__ out) {
    int i = blockIdx.x * blockDim.x + threadIdx.x;
    if (i >= NG * NOUT) return;
    int g = i / NOUT, o = i - g * NOUT;
    float inv = 1.0f / fmaxf(g_cnt[g], 1.0f);
    const float* p = &g_pool[g * HID];
    float s = 0.f;
#pragma unroll 8
    for (int k = 0; k < HID; k++) s += p[k] * Wout[k * NOUT + o];
    out[i] = s * inv + bout[o];
}

// ---------------- launch -----------------------------------------------------
extern "C" void kernel_launch(void* const* d_in, const int* in_sizes, int n_in,
                              void* d_out, int out_size) {
    const float* x     = (const float*)d_in[0];
    const int*   ei    = (const int*)d_in[1];
    const int*   batch = (const int*)d_in[2];
    const float* W0 = (const float*)d_in[3];
    const float* b0 = (const float*)d_in[4];
    const float* ga0 = (const float*)d_in[5];
    const float* be0 = (const float*)d_in[6];
    const float* me0 = (const float*)d_in[7];
    const float* va0 = (const float*)d_in[8];
    const float* W1 = (const float*)d_in[9];
    const float* b1 = (const float*)d_in[10];
    const float* ga1 = (const float*)d_in[11];
    const float* be1 = (const float*)d_in[12];
    const float* me1 = (const float*)d_in[13];
    const float* va1 = (const float*)d_in[14];
    const float* W2 = (const float*)d_in[15];
    const float* b2 = (const float*)d_in[16];
    const float* ga2 = (const float*)d_in[17];
    const float* be2 = (const float*)d_in[18];
    const float* me2 = (const float*)d_in[19];
    const float* va2 = (const float*)d_in[20];
    const float* Wout = (const float*)d_in[21];
    const float* bout = (const float*)d_in[22];
    float* out = (float*)d_out;

    const int* row = ei;
    const int* col = ei + NE;

    cudaFuncSetAttribute(k_mma<false>, cudaFuncAttributeMaxDynamicSharedMemorySize, SM_MMA_BYTES);
    cudaFuncSetAttribute(k_mma<true>,  cudaFuncAttributeMaxDynamicSharedMemorySize, SM_MMA_BYTES);

    // degrees, counts, CSR
    k_zero<<<(NG * HID + 255) / 256, 256>>>();
    k_hist<<<(NE + 255) / 256, 256>>>(col, batch);
    k_dinv<<<(NN + 255) / 256, 256>>>();
    k_scan1<<<NB_SCAN, 256>>>();
    k_scan2<<<1, 256>>>();
    k_scan3<<<(NN + 255) / 256, 256>>>();
    k_fill<<<(NE + 255) / 256, 256>>>(row, col);

    k_affine<<<1, 128>>>(b0, ga0, be0, me0, va0, 0);
    k_affine<<<1, 128>>>(b1, ga1, be1, me1, va1, 1);
    k_affine<<<1, 128>>>(b2, ga2, be2, me2, va2, 2);

    // layer 0: xs = dinv*x, CSR aggregate -> aggA, GEMM -> hs
    k_xs<<<(NN * 8 + 255) / 256, 256>>>(x);
    k_agg0<<<(NN * 8 + 255) / 256, 256>>>();
    k_gemm0<<<MPAD / 64, 256>>>(W0);

    // layer 1: CSR aggregate hs -> aggP; mma -> hs
    k_agg_h<false><<<(NN * 32 + 255) / 256, 256>>>();
    k_mma<false><<<MPAD / 128, 256, SM_MMA_BYTES>>>(W1, 1, batch);

    // layer 2: CSR aggregate hs -> aggQ; mma -> pool atomics
    k_agg_h<true><<<(NN * 32 + 255) / 256, 256>>>();
    k_mma<true><<<MPAD / 128, 256, SM_MMA_BYTES>>>(W2, 2, batch);

    // output
    k_out<<<(NG * NOUT + 255) / 256, 256>>>(Wout, bout, out);
}